// round 3
// baseline (speedup 1.0000x reference)
#include <cuda_runtime.h>

// Problem shape (fixed by setup_inputs): B=1, C=32, H=128, W=256, D=48
#define C_ 32
#define H_ 128
#define W_ 256
#define D_ 48
#define WQ_ (W_ / 4)

// Scratch: y transposed to [H, W, C] so channels are contiguous (16B per c-quad).
// 128*256*32 floats = 4 MB.
__device__ float g_yT[(size_t)H_ * W_ * C_];

// ---------------------------------------------------------------------------
// Pre-pass: transpose y [C,H,W] -> yT [H,W,C]. Standard smem tile transpose,
// coalesced on both sides. ~8 MB total traffic, negligible.
// ---------------------------------------------------------------------------
__global__ void transpose_y_kernel(const float* __restrict__ y) {
    __shared__ float tile[32][33];
    const int h  = blockIdx.y;
    const int w0 = blockIdx.x * 32;
    const int tx = threadIdx.x;   // 0..31
    const int ty = threadIdx.y;   // 0..7

#pragma unroll
    for (int i = 0; i < 32; i += 8) {
        // read: c = ty+i, w = w0+tx  (coalesced over w)
        tile[ty + i][tx] = y[(size_t)(ty + i) * (H_ * W_) + (size_t)h * W_ + w0 + tx];
    }
    __syncthreads();
#pragma unroll
    for (int i = 0; i < 32; i += 8) {
        // write: w = w0+ty+i, c = tx  (coalesced over c)
        g_yT[((size_t)h * W_ + (w0 + ty + i)) * C_ + tx] = tile[tx][ty + i];
    }
}

// ---------------------------------------------------------------------------
// Main kernel. One thread = one (h, d, w-quad). Index order (h, d, wq) so each
// 256-thread block touches exactly one h => two y rows => 64 KB L1-resident
// gather working set. All x loads, disp loads and output stores are float4.
// ---------------------------------------------------------------------------
__global__ __launch_bounds__(256)
void cost_volume_kernel(const float* __restrict__ x,
                        const float* __restrict__ disp,
                        float* __restrict__ out) {
    const int idx = blockIdx.x * blockDim.x + threadIdx.x;
    const int wq  = idx % WQ_;
    const int d   = (idx / WQ_) % D_;
    const int h   = idx / (WQ_ * D_);
    const int w0  = wq * 4;

    // --- vertical sample coordinate (depends only on h), matching reference ---
    // gy = h / ((H-1)/2) - 1 ; iy = ((gy+1)*H - 1) * 0.5
    const float gy  = (float)h / ((H_ - 1.0f) / 2.0f) - 1.0f;
    const float iy  = ((gy + 1.0f) * (float)H_ - 1.0f) * 0.5f;
    const float fy0 = floorf(iy);
    const float wy  = iy - fy0;
    const int y0i = (int)fy0;
    const int y1i = y0i + 1;
    const float my0 = (y0i >= 0 && y0i < H_) ? 1.0f : 0.0f;
    const float my1 = (y1i >= 0 && y1i < H_) ? 1.0f : 0.0f;
    const int yc0 = min(max(y0i, 0), H_ - 1);
    const int yc1 = min(max(y1i, 0), H_ - 1);

    // --- per-w horizontal coordinates and weights (shared across all C) ---
    const float4 dv = *reinterpret_cast<const float4*>(
        disp + ((size_t)d * H_ + h) * W_ + w0);
    const float dvv[4] = {dv.x, dv.y, dv.z, dv.w};

    float w00[4], w01[4], w10[4], w11[4];
    int   o00[4], o01[4], o10[4], o11[4];
#pragma unroll
    for (int j = 0; j < 4; j++) {
        const float cur_x = (float)(w0 + j) - dvv[j];
        const float gx    = cur_x / ((W_ - 1.0f) / 2.0f) - 1.0f;
        const float ix    = ((gx + 1.0f) * (float)W_ - 1.0f) * 0.5f;
        const float fx0   = floorf(ix);
        const float wx    = ix - fx0;
        const int x0i = (int)fx0;
        const int x1i = x0i + 1;
        const float mx0 = (x0i >= 0 && x0i < W_) ? 1.0f : 0.0f;
        const float mx1 = (x1i >= 0 && x1i < W_) ? 1.0f : 0.0f;
        const int xc0 = min(max(x0i, 0), W_ - 1);
        const int xc1 = min(max(x1i, 0), W_ - 1);

        const float a = 1.0f - wx;
        const float b = wx;
        const float p = 1.0f - wy;
        const float q = wy;
        // zeros padding: fold per-corner mask into the weight
        w00[j] = a * p * mx0 * my0;
        w01[j] = b * p * mx1 * my0;
        w10[j] = a * q * mx0 * my1;
        w11[j] = b * q * mx1 * my1;
        // base element offsets into yT [H,W,C]
        o00[j] = (yc0 * W_ + xc0) * C_;
        o01[j] = (yc0 * W_ + xc1) * C_;
        o10[j] = (yc1 * W_ + xc0) * C_;
        o11[j] = (yc1 * W_ + xc1) * C_;
    }

    const size_t HW  = (size_t)H_ * W_;
    const size_t DHW = (size_t)D_ * HW;
    const size_t pos = ((size_t)d * H_ + h) * W_ + w0;   // offset within one c-plane
    const size_t xrow = (size_t)h * W_ + w0;

    // --- channel loop in quads of 4 (one LDG.128 per corner per w) ---
    for (int cq = 0; cq < C_ / 4; cq++) {
        const int cb = cq * 4;
        float acc[4][4];   // [w_lane][channel-in-quad]
#pragma unroll
        for (int j = 0; j < 4; j++) {
            const float4 v00 = *reinterpret_cast<const float4*>(&g_yT[o00[j] + cb]);
            const float4 v01 = *reinterpret_cast<const float4*>(&g_yT[o01[j] + cb]);
            const float4 v10 = *reinterpret_cast<const float4*>(&g_yT[o10[j] + cb]);
            const float4 v11 = *reinterpret_cast<const float4*>(&g_yT[o11[j] + cb]);
            acc[j][0] = w00[j]*v00.x + w01[j]*v01.x + w10[j]*v10.x + w11[j]*v11.x;
            acc[j][1] = w00[j]*v00.y + w01[j]*v01.y + w10[j]*v10.y + w11[j]*v11.y;
            acc[j][2] = w00[j]*v00.z + w01[j]*v01.z + w10[j]*v10.z + w11[j]*v11.z;
            acc[j][3] = w00[j]*v00.w + w01[j]*v01.w + w10[j]*v10.w + w11[j]*v11.w;
        }
#pragma unroll
        for (int c = 0; c < 4; c++) {
            // warped half: out[C + cb + c, d, h, w0..w0+3]
            const float4 ov = make_float4(acc[0][c], acc[1][c], acc[2][c], acc[3][c]);
            *reinterpret_cast<float4*>(out + (size_t)(C_ + cb + c) * DHW + pos) = ov;
            // left half: broadcast of x over D: out[cb + c, d, h, w0..w0+3]
            const float4 xv = *reinterpret_cast<const float4*>(
                x + (size_t)(cb + c) * HW + xrow);
            *reinterpret_cast<float4*>(out + (size_t)(cb + c) * DHW + pos) = xv;
        }
    }
}

// ---------------------------------------------------------------------------
// Launch: transpose pre-pass then main kernel. Both graph-capturable,
// allocation-free (scratch is a __device__ global).
// ---------------------------------------------------------------------------
extern "C" void kernel_launch(void* const* d_in, const int* in_sizes, int n_in,
                              void* d_out, int out_size) {
    (void)in_sizes; (void)n_in; (void)out_size;
    const float* x    = (const float*)d_in[0];
    const float* y    = (const float*)d_in[1];
    const float* disp = (const float*)d_in[2];
    float* out = (float*)d_out;

    dim3 tb(32, 8);
    dim3 tg(W_ / 32, H_);
    transpose_y_kernel<<<tg, tb>>>(y);

    const int total  = H_ * D_ * WQ_;          // 393,216 threads
    const int blocks = total / 256;            // 1536 blocks
    cost_volume_kernel<<<blocks, 256>>>(x, disp, out);
}

// round 4
// speedup vs baseline: 2.0314x; 2.0314x over previous
#include <cuda_runtime.h>

// Problem shape (fixed by setup_inputs): B=1, C=32, H=128, W=256, D=48
#define C_ 32
#define H_ 128
#define W_ 256
#define D_ 48
#define HW_  (H_ * W_)
#define DHW_ (D_ * HW_)

// Scratch: y transposed to [H, W, C] so one bilinear corner = 32 contiguous
// floats = one 128B line.  128*256*32 floats = 4 MB.
__device__ float g_yT[(size_t)H_ * W_ * C_];

// ---------------------------------------------------------------------------
// Pre-pass: transpose y [C,H,W] -> yT [H,W,C]. Coalesced both sides, ~3us.
// ---------------------------------------------------------------------------
__global__ void transpose_y_kernel(const float* __restrict__ y) {
    __shared__ float tile[32][33];
    const int h  = blockIdx.y;
    const int w0 = blockIdx.x * 32;
    const int tx = threadIdx.x;   // 0..31
    const int ty = threadIdx.y;   // 0..7

#pragma unroll
    for (int i = 0; i < 32; i += 8)
        tile[ty + i][tx] = y[(ty + i) * HW_ + h * W_ + w0 + tx];
    __syncthreads();
#pragma unroll
    for (int i = 0; i < 32; i += 8)
        g_yT[((size_t)h * W_ + (w0 + ty + i)) * C_ + tx] = tile[tx][ty + i];
}

// ---------------------------------------------------------------------------
// Main kernel: one block per (d, h). 256 threads.
//  Phase 0: thread t computes weights/offsets for w=t  -> smem (no redundancy)
//  Phase 1: warps gather with lanes spanning channels: warp = 4 positions x
//           8 channel-quads; every LDG.128 uses 100% of its wavefronts.
//           Results go to an xor-swizzled smem tile (conflict-free STS.128).
//  Phase 2: transposed read (conflict-free via swizzle + intra-quad rotation),
//           STG.32 with lanes = consecutive w (fully coalesced HBM writes).
//  Left half: straight float4 copy of x broadcast over d.
// ---------------------------------------------------------------------------
__global__ __launch_bounds__(256)
void cost_volume_kernel(const float* __restrict__ x,
                        const float* __restrict__ disp,
                        float* __restrict__ out) {
    const int h = blockIdx.x;
    const int d = blockIdx.y;
    const int t = threadIdx.x;          // 0..255
    const int wp   = t >> 5;            // warp id 0..7
    const int lane = t & 31;

    __shared__ float4 swts[W_];         // per-w corner weights (masks folded)
    __shared__ int4   soff[W_];         // per-w corner base offsets into yT
    __shared__ float4 stile4[W_ * 8];   // 256 w x 32 c, swizzled, 32KB
    float* stile = (float*)stile4;

    // ---------------- Phase 0: weights & offsets for w = t ----------------
    {
        const int w = t;
        const float gy  = (float)h / ((H_ - 1.0f) / 2.0f) - 1.0f;
        const float iy  = ((gy + 1.0f) * (float)H_ - 1.0f) * 0.5f;
        const float fy0 = floorf(iy);
        const float wy  = iy - fy0;
        const int y0i = (int)fy0;
        const int y1i = y0i + 1;
        const float my0 = (y0i >= 0 && y0i < H_) ? 1.0f : 0.0f;
        const float my1 = (y1i >= 0 && y1i < H_) ? 1.0f : 0.0f;
        const int yc0 = min(max(y0i, 0), H_ - 1);
        const int yc1 = min(max(y1i, 0), H_ - 1);

        const float dv    = disp[(d * H_ + h) * W_ + w];
        const float cur_x = (float)w - dv;
        const float gx    = cur_x / ((W_ - 1.0f) / 2.0f) - 1.0f;
        const float ix    = ((gx + 1.0f) * (float)W_ - 1.0f) * 0.5f;
        const float fx0   = floorf(ix);
        const float wx    = ix - fx0;
        const int x0i = (int)fx0;
        const int x1i = x0i + 1;
        const float mx0 = (x0i >= 0 && x0i < W_) ? 1.0f : 0.0f;
        const float mx1 = (x1i >= 0 && x1i < W_) ? 1.0f : 0.0f;
        const int xc0 = min(max(x0i, 0), W_ - 1);
        const int xc1 = min(max(x1i, 0), W_ - 1);

        const float a = 1.0f - wx, b = wx;
        const float p = 1.0f - wy, q = wy;
        swts[w] = make_float4(a * p * mx0 * my0, b * p * mx1 * my0,
                              a * q * mx0 * my1, b * q * mx1 * my1);
        soff[w] = make_int4((yc0 * W_ + xc0) * C_, (yc0 * W_ + xc1) * C_,
                            (yc1 * W_ + xc0) * C_, (yc1 * W_ + xc1) * C_);
    }
    __syncthreads();

    // ---------------- Phase 1: coalesced gathers, lanes = channels --------
    // lane = sub*8 + cq : sub selects 1 of 4 positions, cq = channel quad.
    {
        const int sub = lane >> 3;      // 0..3
        const int cq  = lane & 7;       // 0..7
        const int cq4 = cq << 2;
#pragma unroll
        for (int i = 0; i < 8; i++) {
            const int w = wp * 32 + i * 4 + sub;
            const float4 wt  = swts[w];     // 8-lane broadcast, conflict-free
            const int4   off = soff[w];
            const float4 v00 = *(const float4*)&g_yT[off.x + cq4];
            const float4 v01 = *(const float4*)&g_yT[off.y + cq4];
            const float4 v10 = *(const float4*)&g_yT[off.z + cq4];
            const float4 v11 = *(const float4*)&g_yT[off.w + cq4];
            float4 v;
            v.x = v00.x*wt.x + v01.x*wt.y + v10.x*wt.z + v11.x*wt.w;
            v.y = v00.y*wt.x + v01.y*wt.y + v10.y*wt.z + v11.y*wt.w;
            v.z = v00.z*wt.x + v01.z*wt.y + v10.z*wt.z + v11.z*wt.w;
            v.w = v00.w*wt.x + v01.w*wt.y + v10.w*wt.z + v11.w*wt.w;

            // intra-quad rotation by r = (w>>3)&3 : rv[(k+r)&3] = v[k]
            const int r = (w >> 3) & 3;
            float4 rv = v;
            if      (r == 1) rv = make_float4(v.w, v.x, v.y, v.z);
            else if (r == 2) rv = make_float4(v.z, v.w, v.x, v.y);
            else if (r == 3) rv = make_float4(v.y, v.z, v.w, v.x);

            // quad-level xor swizzle: conflict-free STS.128 and phase-2 reads
            stile4[w * 8 + (cq ^ (w & 7))] = rv;
        }
    }

    // ---------------- Left half: out[c,d,h,:] = x[c,h,:] (float4 copy) ----
    {
        const int rowbase = h * W_;
        const int obase   = d * HW_ + rowbase;
#pragma unroll
        for (int rep = 0; rep < 8; rep++) {
            const int idx = rep * 256 + t;
            const int c   = idx >> 6;          // 0..31
            const int wq  = idx & 63;          // 0..63
            const float4 xv = *(const float4*)(x + c * HW_ + rowbase + wq * 4);
            *(float4*)(out + c * DHW_ + obase + wq * 4) = xv;
        }
    }
    __syncthreads();

    // ---------------- Phase 2: warped half, coalesced stores --------------
    // Warp wp owns w-range [wp*32, wp*32+32), lane = w. Loop over 32 channels.
    {
        const int w   = wp * 32 + lane;
        const int wq7 = w & 7;
        const int r3  = (w >> 3) & 3;
        const int wbase = w * 32;               // float index of this w's row
        float* po = out + C_ * DHW_ + d * HW_ + h * W_ + w;
#pragma unroll
        for (int c = 0; c < C_; c++) {
            const int cq = c >> 2;
            const int k  = c & 3;
            const float val = stile[wbase + ((cq ^ wq7) << 2) + ((k + r3) & 3)];
            *po = val;                          // lanes = consecutive w: 128B
            po += DHW_;
        }
    }
}

// ---------------------------------------------------------------------------
extern "C" void kernel_launch(void* const* d_in, const int* in_sizes, int n_in,
                              void* d_out, int out_size) {
    (void)in_sizes; (void)n_in; (void)out_size;
    const float* x    = (const float*)d_in[0];
    const float* y    = (const float*)d_in[1];
    const float* disp = (const float*)d_in[2];
    float* out = (float*)d_out;

    dim3 tb(32, 8);
    dim3 tg(W_ / 32, H_);
    transpose_y_kernel<<<tg, tb>>>(y);

    dim3 grid(H_, D_);                 // one block per (h, d)
    cost_volume_kernel<<<grid, 256>>>(x, disp, out);
}

// round 7
// speedup vs baseline: 2.2036x; 1.0848x over previous
#include <cuda_runtime.h>

// Problem shape (fixed by setup_inputs): B=1, C=32, H=128, W=256, D=48
#define C_ 32
#define H_ 128
#define W_ 256
#define D_ 48
#define HW_  (H_ * W_)
#define DHW_ (D_ * HW_)
#define WCH_ 128              // w-chunk width (2 chunks per row)

// Scratch: y transposed to [H, W, C] so one bilinear corner = 32 contiguous
// floats = one 128B line.  128*256*32 floats = 4 MB.
__device__ float g_yT[(size_t)H_ * W_ * C_];

// ---------------------------------------------------------------------------
// Pre-pass: transpose y [C,H,W] -> yT [H,W,C]. Coalesced both sides, ~3us.
// ---------------------------------------------------------------------------
__global__ void transpose_y_kernel(const float* __restrict__ y) {
    __shared__ float tile[32][33];
    const int h  = blockIdx.y;
    const int w0 = blockIdx.x * 32;
    const int tx = threadIdx.x;   // 0..31
    const int ty = threadIdx.y;   // 0..7

#pragma unroll
    for (int i = 0; i < 32; i += 8)
        tile[ty + i][tx] = y[(ty + i) * HW_ + h * W_ + w0 + tx];
    __syncthreads();
#pragma unroll
    for (int i = 0; i < 32; i += 8)
        g_yT[((size_t)h * W_ + (w0 + ty + i)) * C_ + tx] = tile[tx][ty + i];
}

// ---------------------------------------------------------------------------
// Main kernel: one block per (h, d). 256 threads, 24KB smem -> 8 blocks/SM.
//  Phase 0: thread t computes weights/offsets for w = t  -> smem broadcast.
//  Per 128-wide w-chunk:
//   Phase 1: lanes = channels gathers (each LDG.128 fully covers 4 lines);
//            scalar STS into [c][w] swizzled tile (conflict-free).
//   Phase 2: one LDS.128 + one STG.128 per (warp, channel): lane*4 = w,
//            fully coalesced 512B stores.
//  Left half: straight float4 copy of x broadcast over d.
// ---------------------------------------------------------------------------
__global__ __launch_bounds__(256)
void cost_volume_kernel(const float* __restrict__ x,
                        const float* __restrict__ disp,
                        float* __restrict__ out) {
    const int h = blockIdx.x;
    const int d = blockIdx.y;
    const int t = threadIdx.x;          // 0..255
    const int wp   = t >> 5;            // warp id 0..7
    const int lane = t & 31;

    __shared__ float4 swts[W_];         // per-w corner weights (masks folded) 4KB
    __shared__ int4   soff[W_];         // per-w corner base offsets           4KB
    __shared__ float  stile[C_ * WCH_]; // [c][w'] swizzled chunk tile        16KB

    // ---------------- Phase 0: weights & offsets for w = t ----------------
    {
        const int w = t;
        const float gy  = (float)h / ((H_ - 1.0f) / 2.0f) - 1.0f;
        const float iy  = ((gy + 1.0f) * (float)H_ - 1.0f) * 0.5f;
        const float fy0 = floorf(iy);
        const float wy  = iy - fy0;
        const int y0i = (int)fy0;
        const int y1i = y0i + 1;
        const float my0 = (y0i >= 0 && y0i < H_) ? 1.0f : 0.0f;
        const float my1 = (y1i >= 0 && y1i < H_) ? 1.0f : 0.0f;
        const int yc0 = min(max(y0i, 0), H_ - 1);
        const int yc1 = min(max(y1i, 0), H_ - 1);

        const float dv    = disp[(d * H_ + h) * W_ + w];
        const float cur_x = (float)w - dv;
        const float gx    = cur_x / ((W_ - 1.0f) / 2.0f) - 1.0f;
        const float ix    = ((gx + 1.0f) * (float)W_ - 1.0f) * 0.5f;
        const float fx0   = floorf(ix);
        const float wx    = ix - fx0;
        const int x0i = (int)fx0;
        const int x1i = x0i + 1;
        const float mx0 = (x0i >= 0 && x0i < W_) ? 1.0f : 0.0f;
        const float mx1 = (x1i >= 0 && x1i < W_) ? 1.0f : 0.0f;
        const int xc0 = min(max(x0i, 0), W_ - 1);
        const int xc1 = min(max(x1i, 0), W_ - 1);

        const float a = 1.0f - wx, b = wx;
        const float p = 1.0f - wy, q = wy;
        swts[w] = make_float4(a * p * mx0 * my0, b * p * mx1 * my0,
                              a * q * mx0 * my1, b * q * mx1 * my1);
        soff[w] = make_int4((yc0 * W_ + xc0) * C_, (yc0 * W_ + xc1) * C_,
                            (yc1 * W_ + xc0) * C_, (yc1 * W_ + xc1) * C_);
    }

    // ---------------- Left half: out[c,d,h,:] = x[c,h,:] (float4 copy) ----
    // (independent of stile/swts; placed here to overlap with barrier drain)
    {
        const int rowbase = h * W_;
        const int obase   = d * HW_ + rowbase;
#pragma unroll
        for (int rep = 0; rep < 8; rep++) {
            const int idx = rep * 256 + t;
            const int c   = idx >> 6;          // 0..31
            const int wq  = idx & 63;          // 0..63
            const float4 xv = *(const float4*)(x + c * HW_ + rowbase + wq * 4);
            *(float4*)(out + c * DHW_ + obase + wq * 4) = xv;
        }
    }
    __syncthreads();

    const int sub = lane >> 3;      // 0..3  (position within iter-quad)
    const int cq  = lane & 7;       // 0..7  (channel quad)
    const int cq4 = cq << 2;

#pragma unroll
    for (int ch = 0; ch < 2; ch++) {
        const int wbase = ch * WCH_;

        // -------- Phase 1: gathers, lanes = channels; scalar STS ----------
#pragma unroll
        for (int i = 0; i < 4; i++) {
            const int wl = wp * 16 + i * 4 + sub;   // 0..127 within chunk
            const int w  = wbase + wl;
            const float4 wt  = swts[w];     // 8-lane broadcast, conflict-free
            const int4   off = soff[w];
            const float4 v00 = *(const float4*)&g_yT[off.x + cq4];
            const float4 v01 = *(const float4*)&g_yT[off.y + cq4];
            const float4 v10 = *(const float4*)&g_yT[off.z + cq4];
            const float4 v11 = *(const float4*)&g_yT[off.w + cq4];
            float4 v;
            v.x = v00.x*wt.x + v01.x*wt.y + v10.x*wt.z + v11.x*wt.w;
            v.y = v00.y*wt.x + v01.y*wt.y + v10.y*wt.z + v11.y*wt.w;
            v.z = v00.z*wt.x + v01.z*wt.y + v10.z*wt.z + v11.z*wt.w;
            v.w = v00.w*wt.x + v01.w*wt.y + v10.w*wt.z + v11.w*wt.w;

            // [c][w'] with quad-xor swizzle: w' = wl ^ (cq<<2)
            const int wsw  = wl ^ (cq << 2);
            float* sp = &stile[cq4 * WCH_ + wsw];
            sp[0 * WCH_] = v.x;
            sp[1 * WCH_] = v.y;
            sp[2 * WCH_] = v.z;
            sp[3 * WCH_] = v.w;
        }
        __syncthreads();

        // -------- Phase 2: vector read + fully coalesced vector store -----
#pragma unroll
        for (int j = 0; j < 4; j++) {
            const int c   = wp + j * 8;            // 0..31
            const int ccq = c >> 2;
            const int wsw = (lane * 4) ^ (ccq << 2);
            const float4 v = *(const float4*)&stile[c * WCH_ + wsw];
            *(float4*)(out + (size_t)(C_ + c) * DHW_ + d * HW_ + h * W_
                       + wbase + lane * 4) = v;
        }
        __syncthreads();   // stile reused by next chunk
    }
}

// ---------------------------------------------------------------------------
extern "C" void kernel_launch(void* const* d_in, const int* in_sizes, int n_in,
                              void* d_out, int out_size) {
    (void)in_sizes; (void)n_in; (void)out_size;
    const float* x    = (const float*)d_in[0];
    const float* y    = (const float*)d_in[1];
    const float* disp = (const float*)d_in[2];
    float* out = (float*)d_out;

    dim3 tb(32, 8);
    dim3 tg(W_ / 32, H_);
    transpose_y_kernel<<<tg, tb>>>(y);

    dim3 grid(H_, D_);                 // one block per (h, d)
    cost_volume_kernel<<<grid, 256>>>(x, disp, out);
}